// round 5
// baseline (speedup 1.0000x reference)
#include <cuda_runtime.h>
#include <cuda_bf16.h>

// RobustPrompt_I: graph prompt + edge pruning
//  in: x[N,128] f32, edge_index[2,E] i32, p_sim[1,128], p_deg[1,128], p_other[1,128]
//  out: x_new[N,128] f32  ++  keep[E] (0/1 as f32)

#define D        128
#define D4       32
#define NCAP     131072
#define ECAP     1048576
#define SIM_THR  0.2f
#define DEG_THR  3.0f
#define PT_THR   0.1f
#define EPSV     1e-8f

__device__ float2 g_cd[NCAP];      // (csum, deg-as-float) per node
__device__ float  g_rinv[NCAP];    // 1/||x_i||
__device__ float4 g_A0[NCAP];      // (x·p_sim, x·p_deg, x·p_other, ||x||^2)
__device__ float  g_dot[ECAP];     // raw dot(x_r, x_c) per edge
__device__ float  g_W[4][4];       // combo -> weight triple over prompts
__device__ float  g_GC[4][4];      // delta_a · delta_b LUT
__device__ float4 g_delta[4][D4];  // the 4 possible delta rows

// ---------- setup (1 warp): nz flags, Gram, weights, delta rows, LUTs ----------
__global__ void setup_kernel(const float* __restrict__ ps,
                             const float* __restrict__ pd,
                             const float* __restrict__ po) {
    int lane = threadIdx.x;
    unsigned full = 0xFFFFFFFFu;
    float4 P[3];
    P[0] = reinterpret_cast<const float4*>(ps)[lane];
    P[1] = reinterpret_cast<const float4*>(pd)[lane];
    P[2] = reinterpret_cast<const float4*>(po)[lane];

    int nz[3];
    #pragma unroll
    for (int k = 0; k < 3; k++) {
        bool z = (P[k].x != 0.f) & (P[k].y != 0.f) & (P[k].z != 0.f) & (P[k].w != 0.f);
        nz[k] = __all_sync(full, z);
    }
    float G[3][3];
    #pragma unroll
    for (int a = 0; a < 3; a++)
        #pragma unroll
        for (int b = 0; b < 3; b++) {
            float s = P[a].x * P[b].x + P[a].y * P[b].y + P[a].z * P[b].z + P[a].w * P[b].w;
            #pragma unroll
            for (int o = 16; o > 0; o >>= 1) s += __shfl_xor_sync(full, s, o);
            G[a][b] = s;
        }
    float W[4][3];
    #pragma unroll
    for (int idx = 0; idx < 4; idx++) {
        int msim = idx & 1, mdeg = (idx >> 1) & 1, moth = (idx == 0);
        int plen = msim * nz[0] + mdeg * nz[1] + moth * nz[2];
        float inv = (plen > 0) ? (1.0f / (float)plen) : 0.0f;
        W[idx][0] = (float)msim * inv;
        W[idx][1] = (float)mdeg * inv;
        W[idx][2] = (float)moth * inv;
        float4 dl;
        dl.x = W[idx][0]*P[0].x + W[idx][1]*P[1].x + W[idx][2]*P[2].x;
        dl.y = W[idx][0]*P[0].y + W[idx][1]*P[1].y + W[idx][2]*P[2].y;
        dl.z = W[idx][0]*P[0].z + W[idx][1]*P[1].z + W[idx][2]*P[2].z;
        dl.w = W[idx][0]*P[0].w + W[idx][1]*P[1].w + W[idx][2]*P[2].w;
        g_delta[idx][lane] = dl;
    }
    if (lane == 0) {
        for (int idx = 0; idx < 4; idx++) {
            g_W[idx][0] = W[idx][0]; g_W[idx][1] = W[idx][1];
            g_W[idx][2] = W[idx][2]; g_W[idx][3] = 0.f;
        }
        for (int a = 0; a < 4; a++)
            for (int b = 0; b < 4; b++) {
                float s = 0.f;
                for (int k = 0; k < 3; k++)
                    for (int j = 0; j < 3; j++)
                        s += W[a][k] * G[k][j] * W[b][j];
                g_GC[a][b] = s;
            }
    }
}

// ---------- fused: edge raw dots (block-spec) | node stats ----------
__global__ void fused_stats_dot_kernel(const float* __restrict__ x,
                                       const int* __restrict__ ei,
                                       const float* __restrict__ ps,
                                       const float* __restrict__ pd,
                                       const float* __restrict__ po,
                                       int n, int E, int NBe) {
    const float4* X = reinterpret_cast<const float4*>(x);
    if ((int)blockIdx.x < NBe) {
        // ---- edge dot: 2 edges per 8-lane group, 16 loads in flight ----
        int t   = blockIdx.x * blockDim.x + threadIdx.x;
        int g   = t >> 3;
        int sub = t & 7;
        int e0  = g * 2;
        int e1  = e0 + 1;
        if (e0 >= E) return;
        bool has1 = (e1 < E);
        int r0 = __ldg(&ei[e0]);
        int c0 = __ldg(&ei[E + e0]);
        int r1 = has1 ? __ldg(&ei[e1]) : r0;
        int c1 = has1 ? __ldg(&ei[E + e1]) : c0;

        const float4* Ar0 = X + (size_t)r0 * D4 + sub;
        const float4* Bc0 = X + (size_t)c0 * D4 + sub;
        const float4* Ar1 = X + (size_t)r1 * D4 + sub;
        const float4* Bc1 = X + (size_t)c1 * D4 + sub;

        float4 a0[4], b0[4], a1[4], b1[4];
        #pragma unroll
        for (int k = 0; k < 4; k++) a0[k] = __ldg(Ar0 + 8 * k);
        #pragma unroll
        for (int k = 0; k < 4; k++) b0[k] = __ldg(Bc0 + 8 * k);
        #pragma unroll
        for (int k = 0; k < 4; k++) a1[k] = __ldg(Ar1 + 8 * k);
        #pragma unroll
        for (int k = 0; k < 4; k++) b1[k] = __ldg(Bc1 + 8 * k);

        float s0 = 0.f, s1 = 0.f;
        #pragma unroll
        for (int k = 0; k < 4; k++) {
            s0 += a0[k].x*b0[k].x + a0[k].y*b0[k].y + a0[k].z*b0[k].z + a0[k].w*b0[k].w;
            s1 += a1[k].x*b1[k].x + a1[k].y*b1[k].y + a1[k].z*b1[k].z + a1[k].w*b1[k].w;
        }
        #pragma unroll
        for (int o = 4; o > 0; o >>= 1) {
            s0 += __shfl_xor_sync(0xFFFFFFFFu, s0, o);
            s1 += __shfl_xor_sync(0xFFFFFFFFu, s1, o);
        }
        if (sub == 0) {
            g_dot[e0] = s0;
            if (has1) g_dot[e1] = s1;
        }
    } else {
        // ---- node stats (warp/node): rinv, A0, zero cd ----
        int w    = ((blockIdx.x - NBe) * blockDim.x + threadIdx.x) >> 5;
        int lane = threadIdx.x & 31;
        if (w >= n) return;
        float4 xv = X[(size_t)w * D4 + lane];
        float4 P0 = reinterpret_cast<const float4*>(ps)[lane];
        float4 P1 = reinterpret_cast<const float4*>(pd)[lane];
        float4 P2 = reinterpret_cast<const float4*>(po)[lane];

        float ss = xv.x*xv.x + xv.y*xv.y + xv.z*xv.z + xv.w*xv.w;
        float d0 = xv.x*P0.x + xv.y*P0.y + xv.z*P0.z + xv.w*P0.w;
        float d1 = xv.x*P1.x + xv.y*P1.y + xv.z*P1.z + xv.w*P1.w;
        float d2 = xv.x*P2.x + xv.y*P2.y + xv.z*P2.z + xv.w*P2.w;
        #pragma unroll
        for (int o = 16; o > 0; o >>= 1) {
            ss += __shfl_xor_sync(0xFFFFFFFFu, ss, o);
            d0 += __shfl_xor_sync(0xFFFFFFFFu, d0, o);
            d1 += __shfl_xor_sync(0xFFFFFFFFu, d1, o);
            d2 += __shfl_xor_sync(0xFFFFFFFFu, d2, o);
        }
        if (lane == 0) {
            g_rinv[w] = rsqrtf(ss);
            g_A0[w]   = make_float4(d0, d1, d2, ss);
            g_cd[w]   = make_float2(0.f, 0.f);
        }
    }
}

// ---------- scatter: normalized cos + degree atomics (2 edges/thread) ----------
__global__ void scatter_kernel(const int* __restrict__ ei, int E) {
    int t  = blockIdx.x * blockDim.x + threadIdx.x;
    int e0 = t * 2;
    int e1 = e0 + 1;
    if (e0 >= E) return;
    bool has1 = (e1 < E);
    int r0 = __ldg(&ei[e0]);
    int c0 = __ldg(&ei[E + e0]);
    int r1 = has1 ? __ldg(&ei[e1]) : r0;
    int c1 = has1 ? __ldg(&ei[E + e1]) : c0;
    float dt0 = g_dot[e0];
    float dt1 = has1 ? g_dot[e1] : 0.f;
    float i0r = g_rinv[r0], i0c = g_rinv[c0];
    float i1r = g_rinv[r1], i1c = g_rinv[c1];
    float sn0 = dt0 * i0r * i0c;
    atomicAdd(&g_cd[c0].x, sn0);
    atomicAdd(&g_cd[c0].y, 1.0f);
    if (has1) {
        float sn1 = dt1 * i1r * i1c;
        atomicAdd(&g_cd[c1].x, sn1);
        atomicAdd(&g_cd[c1].y, 1.0f);
    }
}

// combo index + 1/||x_new|| from per-node stats (inlined at use sites)
__device__ __forceinline__ int combo_of(float2 cd) {
    bool msim = (cd.y > 0.f) && ((cd.x / cd.y) <= SIM_THR);
    bool mdeg = (cd.y <= DEG_THR);
    return (int)msim | ((int)mdeg << 1);
}

// ---------- fused finish: node write | edge2, both recompute combos ----------
__global__ void finish_kernel(const float* __restrict__ x,
                              const int* __restrict__ ei,
                              float* __restrict__ out,
                              float* __restrict__ keep,
                              int n, int E, int NBn) {
    if ((int)blockIdx.x < NBn) {
        // ---- node write: 16 nodes/block, 16 lanes/node, 2 float4/thread ----
        int tid  = threadIdx.x;
        int node = blockIdx.x * 16 + (tid >> 4);
        if (node >= n) return;
        int j = tid & 15;
        int idx = combo_of(g_cd[node]);
        const float4* Xr = reinterpret_cast<const float4*>(x) + (size_t)node * D4;
        float4 xv0 = __ldg(Xr + j);
        float4 xv1 = __ldg(Xr + j + 16);
        float4 dl0 = g_delta[idx][j];
        float4 dl1 = g_delta[idx][j + 16];
        xv0.x += dl0.x; xv0.y += dl0.y; xv0.z += dl0.z; xv0.w += dl0.w;
        xv1.x += dl1.x; xv1.y += dl1.y; xv1.z += dl1.z; xv1.w += dl1.w;
        float4* Or = reinterpret_cast<float4*>(out) + (size_t)node * D4;
        Or[j]      = xv0;
        Or[j + 16] = xv1;
    } else {
        // ---- edge2: decomposed cosine -> keep (thread/edge) ----
        __shared__ float sW[4][4];
        __shared__ float sGC[4][4];
        if (threadIdx.x < 16) {
            sW[threadIdx.x >> 2][threadIdx.x & 3]  = g_W[threadIdx.x >> 2][threadIdx.x & 3];
            sGC[threadIdx.x >> 2][threadIdx.x & 3] = g_GC[threadIdx.x >> 2][threadIdx.x & 3];
        }
        __syncthreads();
        int e = (blockIdx.x - NBn) * blockDim.x + threadIdx.x;
        if (e >= E) return;
        int r = __ldg(&ei[e]);
        int c = __ldg(&ei[E + e]);
        float dot = g_dot[e];
        float2 cdr = g_cd[r];
        float2 cdc = g_cd[c];
        float4 Ar = g_A0[r];   // (d0,d1,d2,||x||^2)
        float4 Ac = g_A0[c];
        int cr = combo_of(cdr);
        int cc = combo_of(cdc);
        float xddr = sW[cr][0]*Ar.x + sW[cr][1]*Ar.y + sW[cr][2]*Ar.z;
        float xddc = sW[cc][0]*Ac.x + sW[cc][1]*Ac.y + sW[cc][2]*Ac.z;
        float nr2 = Ar.w + 2.0f * xddr + sGC[cr][cr];
        float nc2 = Ac.w + 2.0f * xddc + sGC[cc][cc];
        float rir = 1.0f / fmaxf(sqrtf(fmaxf(nr2, 0.f)), EPSV);
        float ric = 1.0f / fmaxf(sqrtf(fmaxf(nc2, 0.f)), EPSV);
        float num = dot
                  + Ar.x * sW[cc][0] + Ar.y * sW[cc][1] + Ar.z * sW[cc][2]
                  + Ac.x * sW[cr][0] + Ac.y * sW[cr][1] + Ac.z * sW[cr][2]
                  + sGC[cr][cc];
        float cosv = num * rir * ric;
        keep[e] = (cosv >= PT_THR) ? 1.0f : 0.0f;
    }
}

extern "C" void kernel_launch(void* const* d_in, const int* in_sizes, int n_in,
                              void* d_out, int out_size) {
    const float* x  = (const float*)d_in[0];
    const int*   ei = (const int*)d_in[1];
    const float* ps = (const float*)d_in[2];
    const float* pd = (const float*)d_in[3];
    const float* po = (const float*)d_in[4];
    float* out = (float*)d_out;

    int N = in_sizes[0] / D;
    int E = in_sizes[1] / 2;

    setup_kernel<<<1, 32>>>(ps, pd, po);

    int NBe = ((E + 1) / 2 * 8 + 255) / 256;   // edge-dot blocks (64 edges each)
    int NBa = (N + 7) / 8;                     // node-stat blocks (8 nodes each)
    fused_stats_dot_kernel<<<NBe + NBa, 256>>>(x, ei, ps, pd, po, N, E, NBe);

    scatter_kernel<<<((E + 1) / 2 + 255) / 256, 256>>>(ei, E);

    int NBn = (N + 15) / 16;
    bool do_keep = ((long long)out_size >= (long long)N * D + E);
    int NBe2 = do_keep ? (E + 255) / 256 : 0;
    float* keep = out + (size_t)N * D;
    finish_kernel<<<NBn + NBe2, 256>>>(x, ei, out, keep, N, E, NBn);
}

// round 6
// speedup vs baseline: 1.1197x; 1.1197x over previous
#include <cuda_runtime.h>
#include <cuda_bf16.h>

// RobustPrompt_I: graph prompt + edge pruning
//  in: x[N,128] f32, edge_index[2,E] i32, p_sim[1,128], p_deg[1,128], p_other[1,128]
//  out: x_new[N,128] f32  ++  keep[E] (0/1 as f32)

#define D        128
#define D4       32
#define NCAP     131072
#define ECAP     1048576
#define SIM_THR  0.2f
#define DEG_THR  3.0f
#define PT_THR   0.1f
#define EPSV     1e-8f

__device__ float2 g_cd[NCAP];      // (csum, deg-as-float) per node
__device__ float4 g_A0[NCAP];      // (x·p_sim, x·p_deg, x·p_other, ||x||^2)
__device__ float  g_dot[ECAP];     // raw dot(x_r, x_c) per edge
__device__ float  g_W[4][4];       // combo -> weight triple over prompts
__device__ float  g_GC[4][4];      // delta_a · delta_b LUT
__device__ float4 g_delta[4][D4];  // the 4 possible delta rows

// ---------- setup body (1 warp): nz flags, Gram, weights, delta rows, LUTs ----------
__device__ __forceinline__ void setup_body(const float* __restrict__ ps,
                                           const float* __restrict__ pd,
                                           const float* __restrict__ po,
                                           int lane) {
    unsigned full = 0xFFFFFFFFu;
    float4 P[3];
    P[0] = reinterpret_cast<const float4*>(ps)[lane];
    P[1] = reinterpret_cast<const float4*>(pd)[lane];
    P[2] = reinterpret_cast<const float4*>(po)[lane];

    int nz[3];
    #pragma unroll
    for (int k = 0; k < 3; k++) {
        bool z = (P[k].x != 0.f) & (P[k].y != 0.f) & (P[k].z != 0.f) & (P[k].w != 0.f);
        nz[k] = __all_sync(full, z);
    }
    float G[3][3];
    #pragma unroll
    for (int a = 0; a < 3; a++)
        #pragma unroll
        for (int b = 0; b < 3; b++) {
            float s = P[a].x * P[b].x + P[a].y * P[b].y + P[a].z * P[b].z + P[a].w * P[b].w;
            #pragma unroll
            for (int o = 16; o > 0; o >>= 1) s += __shfl_xor_sync(full, s, o);
            G[a][b] = s;
        }
    float W[4][3];
    #pragma unroll
    for (int idx = 0; idx < 4; idx++) {
        int msim = idx & 1, mdeg = (idx >> 1) & 1, moth = (idx == 0);
        int plen = msim * nz[0] + mdeg * nz[1] + moth * nz[2];
        float inv = (plen > 0) ? (1.0f / (float)plen) : 0.0f;
        W[idx][0] = (float)msim * inv;
        W[idx][1] = (float)mdeg * inv;
        W[idx][2] = (float)moth * inv;
        float4 dl;
        dl.x = W[idx][0]*P[0].x + W[idx][1]*P[1].x + W[idx][2]*P[2].x;
        dl.y = W[idx][0]*P[0].y + W[idx][1]*P[1].y + W[idx][2]*P[2].y;
        dl.z = W[idx][0]*P[0].z + W[idx][1]*P[1].z + W[idx][2]*P[2].z;
        dl.w = W[idx][0]*P[0].w + W[idx][1]*P[1].w + W[idx][2]*P[2].w;
        g_delta[idx][lane] = dl;
    }
    if (lane == 0) {
        for (int idx = 0; idx < 4; idx++) {
            g_W[idx][0] = W[idx][0]; g_W[idx][1] = W[idx][1];
            g_W[idx][2] = W[idx][2]; g_W[idx][3] = 0.f;
        }
        for (int a = 0; a < 4; a++)
            for (int b = 0; b < 4; b++) {
                float s = 0.f;
                for (int k = 0; k < 3; k++)
                    for (int j = 0; j < 3; j++)
                        s += W[a][k] * G[k][j] * W[b][j];
                g_GC[a][b] = s;
            }
    }
}

// ---------- K1: edges (dot+norms+scatter) | setup | node stats ----------
__global__ void big_kernel(const float* __restrict__ x,
                           const int* __restrict__ ei,
                           const float* __restrict__ ps,
                           const float* __restrict__ pd,
                           const float* __restrict__ po,
                           int n, int E, int NBe) {
    const float4* X = reinterpret_cast<const float4*>(x);
    int bid = blockIdx.x;
    if (bid < NBe) {
        // ---- edge work: 2 edges per 8-lane group ----
        int t   = bid * blockDim.x + threadIdx.x;
        int g   = t >> 3;
        int sub = t & 7;
        int e0  = g * 2;
        int e1  = e0 + 1;
        if (e0 >= E) return;
        bool has1 = (e1 < E);
        int r0 = __ldg(&ei[e0]);
        int c0 = __ldg(&ei[E + e0]);
        int r1 = has1 ? __ldg(&ei[e1]) : r0;
        int c1 = has1 ? __ldg(&ei[E + e1]) : c0;

        const float4* Ar0 = X + (size_t)r0 * D4 + sub;
        const float4* Bc0 = X + (size_t)c0 * D4 + sub;
        const float4* Ar1 = X + (size_t)r1 * D4 + sub;
        const float4* Bc1 = X + (size_t)c1 * D4 + sub;

        float4 a0[4], b0[4], a1[4], b1[4];
        #pragma unroll
        for (int k = 0; k < 4; k++) a0[k] = __ldg(Ar0 + 8 * k);
        #pragma unroll
        for (int k = 0; k < 4; k++) b0[k] = __ldg(Bc0 + 8 * k);
        #pragma unroll
        for (int k = 0; k < 4; k++) a1[k] = __ldg(Ar1 + 8 * k);
        #pragma unroll
        for (int k = 0; k < 4; k++) b1[k] = __ldg(Bc1 + 8 * k);

        float s0 = 0.f, s1 = 0.f;
        float nr0 = 0.f, nc0 = 0.f, nr1 = 0.f, nc1 = 0.f;
        #pragma unroll
        for (int k = 0; k < 4; k++) {
            s0  += a0[k].x*b0[k].x + a0[k].y*b0[k].y + a0[k].z*b0[k].z + a0[k].w*b0[k].w;
            nr0 += a0[k].x*a0[k].x + a0[k].y*a0[k].y + a0[k].z*a0[k].z + a0[k].w*a0[k].w;
            nc0 += b0[k].x*b0[k].x + b0[k].y*b0[k].y + b0[k].z*b0[k].z + b0[k].w*b0[k].w;
            s1  += a1[k].x*b1[k].x + a1[k].y*b1[k].y + a1[k].z*b1[k].z + a1[k].w*b1[k].w;
            nr1 += a1[k].x*a1[k].x + a1[k].y*a1[k].y + a1[k].z*a1[k].z + a1[k].w*a1[k].w;
            nc1 += b1[k].x*b1[k].x + b1[k].y*b1[k].y + b1[k].z*b1[k].z + b1[k].w*b1[k].w;
        }
        #pragma unroll
        for (int o = 4; o > 0; o >>= 1) {
            s0  += __shfl_xor_sync(0xFFFFFFFFu, s0,  o);
            s1  += __shfl_xor_sync(0xFFFFFFFFu, s1,  o);
            nr0 += __shfl_xor_sync(0xFFFFFFFFu, nr0, o);
            nc0 += __shfl_xor_sync(0xFFFFFFFFu, nc0, o);
            nr1 += __shfl_xor_sync(0xFFFFFFFFu, nr1, o);
            nc1 += __shfl_xor_sync(0xFFFFFFFFu, nc1, o);
        }
        if (sub == 0) {
            g_dot[e0] = s0;
            float sn0 = s0 * rsqrtf(nr0) * rsqrtf(nc0);
            atomicAdd(&g_cd[c0].x, sn0);
            atomicAdd(&g_cd[c0].y, 1.0f);
            if (has1) {
                g_dot[e1] = s1;
                float sn1 = s1 * rsqrtf(nr1) * rsqrtf(nc1);
                atomicAdd(&g_cd[c1].x, sn1);
                atomicAdd(&g_cd[c1].y, 1.0f);
            }
        }
    } else if (bid == NBe) {
        // ---- setup (first warp only) ----
        if (threadIdx.x < 32) setup_body(ps, pd, po, threadIdx.x);
    } else {
        // ---- node stats (warp/node): A0 only ----
        int w    = ((bid - NBe - 1) * blockDim.x + threadIdx.x) >> 5;
        int lane = threadIdx.x & 31;
        if (w >= n) return;
        float4 xv = X[(size_t)w * D4 + lane];
        float4 P0 = reinterpret_cast<const float4*>(ps)[lane];
        float4 P1 = reinterpret_cast<const float4*>(pd)[lane];
        float4 P2 = reinterpret_cast<const float4*>(po)[lane];

        float ss = xv.x*xv.x + xv.y*xv.y + xv.z*xv.z + xv.w*xv.w;
        float d0 = xv.x*P0.x + xv.y*P0.y + xv.z*P0.z + xv.w*P0.w;
        float d1 = xv.x*P1.x + xv.y*P1.y + xv.z*P1.z + xv.w*P1.w;
        float d2 = xv.x*P2.x + xv.y*P2.y + xv.z*P2.z + xv.w*P2.w;
        #pragma unroll
        for (int o = 16; o > 0; o >>= 1) {
            ss += __shfl_xor_sync(0xFFFFFFFFu, ss, o);
            d0 += __shfl_xor_sync(0xFFFFFFFFu, d0, o);
            d1 += __shfl_xor_sync(0xFFFFFFFFu, d1, o);
            d2 += __shfl_xor_sync(0xFFFFFFFFu, d2, o);
        }
        if (lane == 0) g_A0[w] = make_float4(d0, d1, d2, ss);
    }
}

// combo index from per-node (csum, deg)
__device__ __forceinline__ int combo_of(float2 cd) {
    bool msim = (cd.y > 0.f) && ((cd.x / cd.y) <= SIM_THR);
    bool mdeg = (cd.y <= DEG_THR);
    return (int)msim | ((int)mdeg << 1);
}

// ---------- K2 finish: node write (MLP4) | edge2 ----------
__global__ void finish_kernel(const float* __restrict__ x,
                              const int* __restrict__ ei,
                              float* __restrict__ out,
                              float* __restrict__ keep,
                              int n, int E, int NBn) {
    if ((int)blockIdx.x < NBn) {
        // ---- node write: 32 nodes/block, 8 lanes/node, 4 float4/thread ----
        int tid  = threadIdx.x;
        int node = blockIdx.x * 32 + (tid >> 3);
        if (node >= n) return;
        int j = tid & 7;
        int idx = combo_of(g_cd[node]);
        const float4* Xr = reinterpret_cast<const float4*>(x) + (size_t)node * D4;
        float4 xv0 = __ldg(Xr + j);
        float4 xv1 = __ldg(Xr + j + 8);
        float4 xv2 = __ldg(Xr + j + 16);
        float4 xv3 = __ldg(Xr + j + 24);
        float4 dl0 = g_delta[idx][j];
        float4 dl1 = g_delta[idx][j + 8];
        float4 dl2 = g_delta[idx][j + 16];
        float4 dl3 = g_delta[idx][j + 24];
        xv0.x += dl0.x; xv0.y += dl0.y; xv0.z += dl0.z; xv0.w += dl0.w;
        xv1.x += dl1.x; xv1.y += dl1.y; xv1.z += dl1.z; xv1.w += dl1.w;
        xv2.x += dl2.x; xv2.y += dl2.y; xv2.z += dl2.z; xv2.w += dl2.w;
        xv3.x += dl3.x; xv3.y += dl3.y; xv3.z += dl3.z; xv3.w += dl3.w;
        float4* Or = reinterpret_cast<float4*>(out) + (size_t)node * D4;
        Or[j]      = xv0;
        Or[j + 8]  = xv1;
        Or[j + 16] = xv2;
        Or[j + 24] = xv3;
    } else {
        // ---- edge2: decomposed cosine -> keep (thread/edge) ----
        __shared__ float sW[4][4];
        __shared__ float sGC[4][4];
        if (threadIdx.x < 16) {
            sW[threadIdx.x >> 2][threadIdx.x & 3]  = g_W[threadIdx.x >> 2][threadIdx.x & 3];
            sGC[threadIdx.x >> 2][threadIdx.x & 3] = g_GC[threadIdx.x >> 2][threadIdx.x & 3];
        }
        __syncthreads();
        int e = (blockIdx.x - NBn) * blockDim.x + threadIdx.x;
        if (e >= E) return;
        int r = __ldg(&ei[e]);
        int c = __ldg(&ei[E + e]);
        float dot = g_dot[e];
        float2 cdr = g_cd[r];
        float2 cdc = g_cd[c];
        float4 Ar = g_A0[r];   // (d0,d1,d2,||x||^2)
        float4 Ac = g_A0[c];
        int cr = combo_of(cdr);
        int cc = combo_of(cdc);
        float xddr = sW[cr][0]*Ar.x + sW[cr][1]*Ar.y + sW[cr][2]*Ar.z;
        float xddc = sW[cc][0]*Ac.x + sW[cc][1]*Ac.y + sW[cc][2]*Ac.z;
        float nr2 = Ar.w + 2.0f * xddr + sGC[cr][cr];
        float nc2 = Ac.w + 2.0f * xddc + sGC[cc][cc];
        float rir = 1.0f / fmaxf(sqrtf(fmaxf(nr2, 0.f)), EPSV);
        float ric = 1.0f / fmaxf(sqrtf(fmaxf(nc2, 0.f)), EPSV);
        float num = dot
                  + Ar.x * sW[cc][0] + Ar.y * sW[cc][1] + Ar.z * sW[cc][2]
                  + Ac.x * sW[cr][0] + Ac.y * sW[cr][1] + Ac.z * sW[cr][2]
                  + sGC[cr][cc];
        float cosv = num * rir * ric;
        keep[e] = (cosv >= PT_THR) ? 1.0f : 0.0f;
    }
}

extern "C" void kernel_launch(void* const* d_in, const int* in_sizes, int n_in,
                              void* d_out, int out_size) {
    const float* x  = (const float*)d_in[0];
    const int*   ei = (const int*)d_in[1];
    const float* ps = (const float*)d_in[2];
    const float* pd = (const float*)d_in[3];
    const float* po = (const float*)d_in[4];
    float* out = (float*)d_out;

    int N = in_sizes[0] / D;
    int E = in_sizes[1] / 2;

    static void* cd_ptr = nullptr;
    if (!cd_ptr) cudaGetSymbolAddress(&cd_ptr, g_cd);
    cudaMemsetAsync(cd_ptr, 0, (size_t)N * sizeof(float2));

    int NBe = ((E + 1) / 2 * 8 + 255) / 256;   // edge blocks (64 edges each)
    int NBa = (N + 7) / 8;                     // node-stat blocks (8 nodes each)
    big_kernel<<<NBe + 1 + NBa, 256>>>(x, ei, ps, pd, po, N, E, NBe);

    int NBn = (N + 31) / 32;
    bool do_keep = ((long long)out_size >= (long long)N * D + E);
    int NBe2 = do_keep ? (E + 255) / 256 : 0;
    float* keep = out + (size_t)N * D;
    finish_kernel<<<NBn + NBe2, 256>>>(x, ei, out, keep, N, E, NBn);
}

// round 7
// speedup vs baseline: 1.2063x; 1.0773x over previous
#include <cuda_runtime.h>
#include <cuda_bf16.h>

// RobustPrompt_I: graph prompt + edge pruning
//  in: x[N,128] f32, edge_index[2,E] i32, p_sim[1,128], p_deg[1,128], p_other[1,128]
//  out: x_new[N,128] f32  ++  keep[E] (0/1 as f32)

#define D        128
#define D4       32
#define NCAP     131072
#define ECAP     1048576
#define SIM_THR  0.2f
#define DEG_THR  3.0f
#define PT_THR   0.1f
#define EPSV     1e-8f

#define NBE      2048        // persistent edge blocks in big_kernel

__device__ float2 g_cd[NCAP];      // (csum, deg-as-float) per node
__device__ float4 g_A0[NCAP];      // (x·p_sim, x·p_deg, x·p_other, ||x||^2)
__device__ float  g_dot[ECAP];     // raw dot(x_r, x_c) per edge
__device__ float  g_W[4][4];       // combo -> weight triple over prompts
__device__ float  g_GC[4][4];      // delta_a · delta_b LUT
__device__ float4 g_delta[4][D4];  // the 4 possible delta rows

// ---------- setup body (1 warp): nz flags, Gram, weights, delta rows, LUTs ----------
__device__ __forceinline__ void setup_body(const float* __restrict__ ps,
                                           const float* __restrict__ pd,
                                           const float* __restrict__ po,
                                           int lane) {
    unsigned full = 0xFFFFFFFFu;
    float4 P[3];
    P[0] = reinterpret_cast<const float4*>(ps)[lane];
    P[1] = reinterpret_cast<const float4*>(pd)[lane];
    P[2] = reinterpret_cast<const float4*>(po)[lane];

    int nz[3];
    #pragma unroll
    for (int k = 0; k < 3; k++) {
        bool z = (P[k].x != 0.f) & (P[k].y != 0.f) & (P[k].z != 0.f) & (P[k].w != 0.f);
        nz[k] = __all_sync(full, z);
    }
    float G[3][3];
    #pragma unroll
    for (int a = 0; a < 3; a++)
        #pragma unroll
        for (int b = 0; b < 3; b++) {
            float s = P[a].x * P[b].x + P[a].y * P[b].y + P[a].z * P[b].z + P[a].w * P[b].w;
            #pragma unroll
            for (int o = 16; o > 0; o >>= 1) s += __shfl_xor_sync(full, s, o);
            G[a][b] = s;
        }
    float W[4][3];
    #pragma unroll
    for (int idx = 0; idx < 4; idx++) {
        int msim = idx & 1, mdeg = (idx >> 1) & 1, moth = (idx == 0);
        int plen = msim * nz[0] + mdeg * nz[1] + moth * nz[2];
        float inv = (plen > 0) ? (1.0f / (float)plen) : 0.0f;
        W[idx][0] = (float)msim * inv;
        W[idx][1] = (float)mdeg * inv;
        W[idx][2] = (float)moth * inv;
        float4 dl;
        dl.x = W[idx][0]*P[0].x + W[idx][1]*P[1].x + W[idx][2]*P[2].x;
        dl.y = W[idx][0]*P[0].y + W[idx][1]*P[1].y + W[idx][2]*P[2].y;
        dl.z = W[idx][0]*P[0].z + W[idx][1]*P[1].z + W[idx][2]*P[2].z;
        dl.w = W[idx][0]*P[0].w + W[idx][1]*P[1].w + W[idx][2]*P[2].w;
        g_delta[idx][lane] = dl;
    }
    if (lane == 0) {
        for (int idx = 0; idx < 4; idx++) {
            g_W[idx][0] = W[idx][0]; g_W[idx][1] = W[idx][1];
            g_W[idx][2] = W[idx][2]; g_W[idx][3] = 0.f;
        }
        for (int a = 0; a < 4; a++)
            for (int b = 0; b < 4; b++) {
                float s = 0.f;
                for (int k = 0; k < 3; k++)
                    for (int j = 0; j < 3; j++)
                        s += W[a][k] * G[k][j] * W[b][j];
                g_GC[a][b] = s;
            }
    }
}

// ---------- K1: edges (pipelined gather+dot+norms+scatter) | setup | node stats ----------
__global__ void big_kernel(const float* __restrict__ x,
                           const int* __restrict__ ei,
                           const float* __restrict__ ps,
                           const float* __restrict__ pd,
                           const float* __restrict__ po,
                           int n, int E) {
    const float4* X = reinterpret_cast<const float4*>(x);
    int bid = blockIdx.x;
    if (bid < NBE) {
        // ---- persistent edge groups: 8 lanes/edge, grid-stride, idx prefetch ----
        int sub     = threadIdx.x & 7;
        int group   = bid * 32 + (threadIdx.x >> 3);
        int ngroups = NBE * 32;

        int e = group;
        int r = 0, c = 0;
        if (e < E) { r = __ldg(&ei[e]); c = __ldg(&ei[E + e]); }
        while (e < E) {
            const float4* Ar = X + (size_t)r * D4 + sub;
            const float4* Bc = X + (size_t)c * D4 + sub;
            float4 a[4], b[4];
            #pragma unroll
            for (int k = 0; k < 4; k++) a[k] = __ldg(Ar + 8 * k);
            #pragma unroll
            for (int k = 0; k < 4; k++) b[k] = __ldg(Bc + 8 * k);

            // prefetch next edge's indices while rows are in flight
            int en = e + ngroups;
            int rn = 0, cn = 0;
            if (en < E) { rn = __ldg(&ei[en]); cn = __ldg(&ei[E + en]); }

            float s = 0.f, nr = 0.f, nc = 0.f;
            #pragma unroll
            for (int k = 0; k < 4; k++) {
                s  += a[k].x*b[k].x + a[k].y*b[k].y + a[k].z*b[k].z + a[k].w*b[k].w;
                nr += a[k].x*a[k].x + a[k].y*a[k].y + a[k].z*a[k].z + a[k].w*a[k].w;
                nc += b[k].x*b[k].x + b[k].y*b[k].y + b[k].z*b[k].z + b[k].w*b[k].w;
            }
            #pragma unroll
            for (int o = 4; o > 0; o >>= 1) {
                s  += __shfl_xor_sync(0xFFFFFFFFu, s,  o);
                nr += __shfl_xor_sync(0xFFFFFFFFu, nr, o);
                nc += __shfl_xor_sync(0xFFFFFFFFu, nc, o);
            }
            if (sub == 0) {
                g_dot[e] = s;
                float sn = s * rsqrtf(nr) * rsqrtf(nc);
                atomicAdd(&g_cd[c].x, sn);
                atomicAdd(&g_cd[c].y, 1.0f);
            }
            e = en; r = rn; c = cn;
        }
    } else if (bid == NBE) {
        // ---- setup (first warp only) ----
        if (threadIdx.x < 32) setup_body(ps, pd, po, threadIdx.x);
    } else {
        // ---- node stats (warp/node): A0 only ----
        int w    = ((bid - NBE - 1) * blockDim.x + threadIdx.x) >> 5;
        int lane = threadIdx.x & 31;
        if (w >= n) return;
        float4 xv = X[(size_t)w * D4 + lane];
        float4 P0 = reinterpret_cast<const float4*>(ps)[lane];
        float4 P1 = reinterpret_cast<const float4*>(pd)[lane];
        float4 P2 = reinterpret_cast<const float4*>(po)[lane];

        float ss = xv.x*xv.x + xv.y*xv.y + xv.z*xv.z + xv.w*xv.w;
        float d0 = xv.x*P0.x + xv.y*P0.y + xv.z*P0.z + xv.w*P0.w;
        float d1 = xv.x*P1.x + xv.y*P1.y + xv.z*P1.z + xv.w*P1.w;
        float d2 = xv.x*P2.x + xv.y*P2.y + xv.z*P2.z + xv.w*P2.w;
        #pragma unroll
        for (int o = 16; o > 0; o >>= 1) {
            ss += __shfl_xor_sync(0xFFFFFFFFu, ss, o);
            d0 += __shfl_xor_sync(0xFFFFFFFFu, d0, o);
            d1 += __shfl_xor_sync(0xFFFFFFFFu, d1, o);
            d2 += __shfl_xor_sync(0xFFFFFFFFu, d2, o);
        }
        if (lane == 0) g_A0[w] = make_float4(d0, d1, d2, ss);
    }
}

// combo index from per-node (csum, deg)
__device__ __forceinline__ int combo_of(float2 cd) {
    bool msim = (cd.y > 0.f) && ((cd.x / cd.y) <= SIM_THR);
    bool mdeg = (cd.y <= DEG_THR);
    return (int)msim | ((int)mdeg << 1);
}

// ---------- K2 finish: node write (MLP4, streaming stores) | edge2 ----------
__global__ void finish_kernel(const float* __restrict__ x,
                              const int* __restrict__ ei,
                              float* __restrict__ out,
                              float* __restrict__ keep,
                              int n, int E, int NBn) {
    if ((int)blockIdx.x < NBn) {
        // ---- node write: 32 nodes/block, 8 lanes/node, 4 float4/thread ----
        int tid  = threadIdx.x;
        int node = blockIdx.x * 32 + (tid >> 3);
        if (node >= n) return;
        int j = tid & 7;
        int idx = combo_of(g_cd[node]);
        const float4* Xr = reinterpret_cast<const float4*>(x) + (size_t)node * D4;
        float4 xv0 = __ldcs(Xr + j);
        float4 xv1 = __ldcs(Xr + j + 8);
        float4 xv2 = __ldcs(Xr + j + 16);
        float4 xv3 = __ldcs(Xr + j + 24);
        float4 dl0 = g_delta[idx][j];
        float4 dl1 = g_delta[idx][j + 8];
        float4 dl2 = g_delta[idx][j + 16];
        float4 dl3 = g_delta[idx][j + 24];
        xv0.x += dl0.x; xv0.y += dl0.y; xv0.z += dl0.z; xv0.w += dl0.w;
        xv1.x += dl1.x; xv1.y += dl1.y; xv1.z += dl1.z; xv1.w += dl1.w;
        xv2.x += dl2.x; xv2.y += dl2.y; xv2.z += dl2.z; xv2.w += dl2.w;
        xv3.x += dl3.x; xv3.y += dl3.y; xv3.z += dl3.z; xv3.w += dl3.w;
        float4* Or = reinterpret_cast<float4*>(out) + (size_t)node * D4;
        __stcs(Or + j,      xv0);
        __stcs(Or + j + 8,  xv1);
        __stcs(Or + j + 16, xv2);
        __stcs(Or + j + 24, xv3);
    } else {
        // ---- edge2: decomposed cosine -> keep (thread/edge) ----
        __shared__ float sW[4][4];
        __shared__ float sGC[4][4];
        if (threadIdx.x < 16) {
            sW[threadIdx.x >> 2][threadIdx.x & 3]  = g_W[threadIdx.x >> 2][threadIdx.x & 3];
            sGC[threadIdx.x >> 2][threadIdx.x & 3] = g_GC[threadIdx.x >> 2][threadIdx.x & 3];
        }
        __syncthreads();
        int e = (blockIdx.x - NBn) * blockDim.x + threadIdx.x;
        if (e >= E) return;
        int r = __ldg(&ei[e]);
        int c = __ldg(&ei[E + e]);
        float dot = g_dot[e];
        float2 cdr = g_cd[r];
        float2 cdc = g_cd[c];
        float4 Ar = g_A0[r];   // (d0,d1,d2,||x||^2)
        float4 Ac = g_A0[c];
        int cr = combo_of(cdr);
        int cc = combo_of(cdc);
        float xddr = sW[cr][0]*Ar.x + sW[cr][1]*Ar.y + sW[cr][2]*Ar.z;
        float xddc = sW[cc][0]*Ac.x + sW[cc][1]*Ac.y + sW[cc][2]*Ac.z;
        float nr2 = Ar.w + 2.0f * xddr + sGC[cr][cr];
        float nc2 = Ac.w + 2.0f * xddc + sGC[cc][cc];
        float rir = 1.0f / fmaxf(sqrtf(fmaxf(nr2, 0.f)), EPSV);
        float ric = 1.0f / fmaxf(sqrtf(fmaxf(nc2, 0.f)), EPSV);
        float num = dot
                  + Ar.x * sW[cc][0] + Ar.y * sW[cc][1] + Ar.z * sW[cc][2]
                  + Ac.x * sW[cr][0] + Ac.y * sW[cr][1] + Ac.z * sW[cr][2]
                  + sGC[cr][cc];
        float cosv = num * rir * ric;
        keep[e] = (cosv >= PT_THR) ? 1.0f : 0.0f;
    }
}

extern "C" void kernel_launch(void* const* d_in, const int* in_sizes, int n_in,
                              void* d_out, int out_size) {
    const float* x  = (const float*)d_in[0];
    const int*   ei = (const int*)d_in[1];
    const float* ps = (const float*)d_in[2];
    const float* pd = (const float*)d_in[3];
    const float* po = (const float*)d_in[4];
    float* out = (float*)d_out;

    int N = in_sizes[0] / D;
    int E = in_sizes[1] / 2;

    static void* cd_ptr = nullptr;
    if (!cd_ptr) cudaGetSymbolAddress(&cd_ptr, g_cd);
    cudaMemsetAsync(cd_ptr, 0, (size_t)N * sizeof(float2));

    int NBa = (N + 7) / 8;                     // node-stat blocks (8 nodes each)
    big_kernel<<<NBE + 1 + NBa, 256>>>(x, ei, ps, pd, po, N, E);

    int NBn = (N + 31) / 32;
    bool do_keep = ((long long)out_size >= (long long)N * D + E);
    int NBe2 = do_keep ? (E + 255) / 256 : 0;
    float* keep = out + (size_t)N * D;
    finish_kernel<<<NBn + NBe2, 256>>>(x, ei, out, keep, N, E, NBn);
}

// round 8
// speedup vs baseline: 1.2381x; 1.0263x over previous
#include <cuda_runtime.h>
#include <cuda_bf16.h>

// RobustPrompt_I: graph prompt + edge pruning
//  in: x[N,128] f32, edge_index[2,E] i32, p_sim[1,128], p_deg[1,128], p_other[1,128]
//  out: x_new[N,128] f32  ++  keep[E] (0/1 as f32)

#define D        128
#define D4       32
#define NCAP     131072
#define ECAP     1048576
#define SIM_THR  0.2f
#define DEG_THR  3.0f
#define PT_THR   0.1f
#define EPSV     1e-8f

#define NBE      2048        // persistent edge blocks in big_kernel

__device__ float2 g_cd[NCAP];      // (csum, deg-as-float) per node
__device__ float4 g_A0[NCAP];      // (x·p_sim, x·p_deg, x·p_other, ||x||^2)
__device__ float  g_dot[ECAP];     // raw dot(x_r, x_c) per edge
__device__ float  g_W[4][4];       // combo -> weight triple over prompts (row=float4)
__device__ float  g_GC[4][4];      // delta_a · delta_b LUT
__device__ float4 g_delta[4][D4];  // the 4 possible delta rows

// ---------- setup body (1 warp): nz flags, Gram, weights, delta rows, LUTs ----------
__device__ __forceinline__ void setup_body(const float* __restrict__ ps,
                                           const float* __restrict__ pd,
                                           const float* __restrict__ po,
                                           int lane) {
    unsigned full = 0xFFFFFFFFu;
    float4 P[3];
    P[0] = reinterpret_cast<const float4*>(ps)[lane];
    P[1] = reinterpret_cast<const float4*>(pd)[lane];
    P[2] = reinterpret_cast<const float4*>(po)[lane];

    int nz[3];
    #pragma unroll
    for (int k = 0; k < 3; k++) {
        bool z = (P[k].x != 0.f) & (P[k].y != 0.f) & (P[k].z != 0.f) & (P[k].w != 0.f);
        nz[k] = __all_sync(full, z);
    }
    float G[3][3];
    #pragma unroll
    for (int a = 0; a < 3; a++)
        #pragma unroll
        for (int b = 0; b < 3; b++) {
            float s = P[a].x * P[b].x + P[a].y * P[b].y + P[a].z * P[b].z + P[a].w * P[b].w;
            #pragma unroll
            for (int o = 16; o > 0; o >>= 1) s += __shfl_xor_sync(full, s, o);
            G[a][b] = s;
        }
    float W[4][3];
    #pragma unroll
    for (int idx = 0; idx < 4; idx++) {
        int msim = idx & 1, mdeg = (idx >> 1) & 1, moth = (idx == 0);
        int plen = msim * nz[0] + mdeg * nz[1] + moth * nz[2];
        float inv = (plen > 0) ? (1.0f / (float)plen) : 0.0f;
        W[idx][0] = (float)msim * inv;
        W[idx][1] = (float)mdeg * inv;
        W[idx][2] = (float)moth * inv;
        float4 dl;
        dl.x = W[idx][0]*P[0].x + W[idx][1]*P[1].x + W[idx][2]*P[2].x;
        dl.y = W[idx][0]*P[0].y + W[idx][1]*P[1].y + W[idx][2]*P[2].y;
        dl.z = W[idx][0]*P[0].z + W[idx][1]*P[1].z + W[idx][2]*P[2].z;
        dl.w = W[idx][0]*P[0].w + W[idx][1]*P[1].w + W[idx][2]*P[2].w;
        g_delta[idx][lane] = dl;
    }
    if (lane == 0) {
        for (int idx = 0; idx < 4; idx++) {
            g_W[idx][0] = W[idx][0]; g_W[idx][1] = W[idx][1];
            g_W[idx][2] = W[idx][2]; g_W[idx][3] = 0.f;
        }
        for (int a = 0; a < 4; a++)
            for (int b = 0; b < 4; b++) {
                float s = 0.f;
                for (int k = 0; k < 3; k++)
                    for (int j = 0; j < 3; j++)
                        s += W[a][k] * G[k][j] * W[b][j];
                g_GC[a][b] = s;
            }
    }
}

// ---------- K1: edges (pipelined gather+dot+norms+scatter) | setup | node stats ----------
__global__ void big_kernel(const float* __restrict__ x,
                           const int* __restrict__ ei,
                           const float* __restrict__ ps,
                           const float* __restrict__ pd,
                           const float* __restrict__ po,
                           int n, int E) {
    const float4* X = reinterpret_cast<const float4*>(x);
    int bid = blockIdx.x;
    if (bid < NBE) {
        int sub     = threadIdx.x & 7;
        int group   = bid * 32 + (threadIdx.x >> 3);
        int ngroups = NBE * 32;

        int e = group;
        int r = 0, c = 0;
        if (e < E) { r = __ldg(&ei[e]); c = __ldg(&ei[E + e]); }
        while (e < E) {
            const float4* Ar = X + (size_t)r * D4 + sub;
            const float4* Bc = X + (size_t)c * D4 + sub;
            float4 a[4], b[4];
            #pragma unroll
            for (int k = 0; k < 4; k++) a[k] = __ldg(Ar + 8 * k);
            #pragma unroll
            for (int k = 0; k < 4; k++) b[k] = __ldg(Bc + 8 * k);

            int en = e + ngroups;
            int rn = 0, cn = 0;
            if (en < E) { rn = __ldg(&ei[en]); cn = __ldg(&ei[E + en]); }

            float s = 0.f, nr = 0.f, nc = 0.f;
            #pragma unroll
            for (int k = 0; k < 4; k++) {
                s  += a[k].x*b[k].x + a[k].y*b[k].y + a[k].z*b[k].z + a[k].w*b[k].w;
                nr += a[k].x*a[k].x + a[k].y*a[k].y + a[k].z*a[k].z + a[k].w*a[k].w;
                nc += b[k].x*b[k].x + b[k].y*b[k].y + b[k].z*b[k].z + b[k].w*b[k].w;
            }
            #pragma unroll
            for (int o = 4; o > 0; o >>= 1) {
                s  += __shfl_xor_sync(0xFFFFFFFFu, s,  o);
                nr += __shfl_xor_sync(0xFFFFFFFFu, nr, o);
                nc += __shfl_xor_sync(0xFFFFFFFFu, nc, o);
            }
            if (sub == 0) {
                g_dot[e] = s;
                float sn = s * rsqrtf(nr) * rsqrtf(nc);
                atomicAdd(&g_cd[c].x, sn);
                atomicAdd(&g_cd[c].y, 1.0f);
            }
            e = en; r = rn; c = cn;
        }
    } else if (bid == NBE) {
        if (threadIdx.x < 32) setup_body(ps, pd, po, threadIdx.x);
    } else {
        int w    = ((bid - NBE - 1) * blockDim.x + threadIdx.x) >> 5;
        int lane = threadIdx.x & 31;
        if (w >= n) return;
        float4 xv = X[(size_t)w * D4 + lane];
        float4 P0 = reinterpret_cast<const float4*>(ps)[lane];
        float4 P1 = reinterpret_cast<const float4*>(pd)[lane];
        float4 P2 = reinterpret_cast<const float4*>(po)[lane];

        float ss = xv.x*xv.x + xv.y*xv.y + xv.z*xv.z + xv.w*xv.w;
        float d0 = xv.x*P0.x + xv.y*P0.y + xv.z*P0.z + xv.w*P0.w;
        float d1 = xv.x*P1.x + xv.y*P1.y + xv.z*P1.z + xv.w*P1.w;
        float d2 = xv.x*P2.x + xv.y*P2.y + xv.z*P2.z + xv.w*P2.w;
        #pragma unroll
        for (int o = 16; o > 0; o >>= 1) {
            ss += __shfl_xor_sync(0xFFFFFFFFu, ss, o);
            d0 += __shfl_xor_sync(0xFFFFFFFFu, d0, o);
            d1 += __shfl_xor_sync(0xFFFFFFFFu, d1, o);
            d2 += __shfl_xor_sync(0xFFFFFFFFu, d2, o);
        }
        if (lane == 0) g_A0[w] = make_float4(d0, d1, d2, ss);
    }
}

// combo index from per-node (csum, deg) — bit-identical to reference masks
__device__ __forceinline__ int combo_of(float2 cd) {
    bool msim = (cd.y > 0.f) && ((cd.x / cd.y) <= SIM_THR);
    bool mdeg = (cd.y <= DEG_THR);
    return (int)msim | ((int)mdeg << 1);
}

// per-edge keep from endpoint records (global L1-hot LUTs)
__device__ __forceinline__ float edge_keep(float dot, float2 cdr, float2 cdc,
                                           float4 Ar, float4 Ac) {
    int cr = combo_of(cdr);
    int cc = combo_of(cdc);
    float4 Wr = *reinterpret_cast<const float4*>(&g_W[cr][0]);
    float4 Wc = *reinterpret_cast<const float4*>(&g_W[cc][0]);
    float xddr = Wr.x*Ar.x + Wr.y*Ar.y + Wr.z*Ar.z;
    float xddc = Wc.x*Ac.x + Wc.y*Ac.y + Wc.z*Ac.z;
    float nr2 = Ar.w + 2.0f * xddr + g_GC[cr][cr];
    float nc2 = Ac.w + 2.0f * xddc + g_GC[cc][cc];
    float rir = 1.0f / fmaxf(sqrtf(fmaxf(nr2, 0.f)), EPSV);
    float ric = 1.0f / fmaxf(sqrtf(fmaxf(nc2, 0.f)), EPSV);
    float num = dot
              + Ar.x * Wc.x + Ar.y * Wc.y + Ar.z * Wc.z
              + Ac.x * Wr.x + Ac.y * Wr.y + Ac.z * Wr.z
              + g_GC[cr][cc];
    float cosv = num * rir * ric;
    return (cosv >= PT_THR) ? 1.0f : 0.0f;
}

// ---------- K2 finish: node write (MLP4) | edge2 (2 edges/thread, batched) ----------
__global__ void finish_kernel(const float* __restrict__ x,
                              const int* __restrict__ ei,
                              float* __restrict__ out,
                              float* __restrict__ keep,
                              int n, int E, int NBn) {
    if ((int)blockIdx.x < NBn) {
        int tid  = threadIdx.x;
        int node = blockIdx.x * 32 + (tid >> 3);
        if (node >= n) return;
        int j = tid & 7;
        int idx = combo_of(g_cd[node]);
        const float4* Xr = reinterpret_cast<const float4*>(x) + (size_t)node * D4;
        float4 xv0 = __ldcs(Xr + j);
        float4 xv1 = __ldcs(Xr + j + 8);
        float4 xv2 = __ldcs(Xr + j + 16);
        float4 xv3 = __ldcs(Xr + j + 24);
        float4 dl0 = g_delta[idx][j];
        float4 dl1 = g_delta[idx][j + 8];
        float4 dl2 = g_delta[idx][j + 16];
        float4 dl3 = g_delta[idx][j + 24];
        xv0.x += dl0.x; xv0.y += dl0.y; xv0.z += dl0.z; xv0.w += dl0.w;
        xv1.x += dl1.x; xv1.y += dl1.y; xv1.z += dl1.z; xv1.w += dl1.w;
        xv2.x += dl2.x; xv2.y += dl2.y; xv2.z += dl2.z; xv2.w += dl2.w;
        xv3.x += dl3.x; xv3.y += dl3.y; xv3.z += dl3.z; xv3.w += dl3.w;
        float4* Or = reinterpret_cast<float4*>(out) + (size_t)node * D4;
        __stcs(Or + j,      xv0);
        __stcs(Or + j + 8,  xv1);
        __stcs(Or + j + 16, xv2);
        __stcs(Or + j + 24, xv3);
    } else {
        // ---- edge2: 2 edges/thread, all gathers issued before compute ----
        int t  = (blockIdx.x - NBn) * blockDim.x + threadIdx.x;
        int e0 = t * 2;
        int e1 = e0 + 1;
        if (e0 >= E) return;
        bool has1 = (e1 < E);

        int r0 = __ldg(&ei[e0]);
        int c0 = __ldg(&ei[E + e0]);
        int r1 = has1 ? __ldg(&ei[e1]) : r0;
        int c1 = has1 ? __ldg(&ei[E + e1]) : c0;
        float dt0 = g_dot[e0];
        float dt1 = has1 ? g_dot[e1] : 0.f;

        float2 cdr0 = g_cd[r0], cdc0 = g_cd[c0];
        float2 cdr1 = g_cd[r1], cdc1 = g_cd[c1];
        float4 Ar0  = g_A0[r0], Ac0  = g_A0[c0];
        float4 Ar1  = g_A0[r1], Ac1  = g_A0[c1];

        float k0 = edge_keep(dt0, cdr0, cdc0, Ar0, Ac0);
        keep[e0] = k0;
        if (has1) {
            float k1 = edge_keep(dt1, cdr1, cdc1, Ar1, Ac1);
            keep[e1] = k1;
        }
    }
}

extern "C" void kernel_launch(void* const* d_in, const int* in_sizes, int n_in,
                              void* d_out, int out_size) {
    const float* x  = (const float*)d_in[0];
    const int*   ei = (const int*)d_in[1];
    const float* ps = (const float*)d_in[2];
    const float* pd = (const float*)d_in[3];
    const float* po = (const float*)d_in[4];
    float* out = (float*)d_out;

    int N = in_sizes[0] / D;
    int E = in_sizes[1] / 2;

    static void* cd_ptr = nullptr;
    if (!cd_ptr) cudaGetSymbolAddress(&cd_ptr, g_cd);
    cudaMemsetAsync(cd_ptr, 0, (size_t)N * sizeof(float2));

    int NBa = (N + 7) / 8;
    big_kernel<<<NBE + 1 + NBa, 256>>>(x, ei, ps, pd, po, N, E);

    int NBn = (N + 31) / 32;
    bool do_keep = ((long long)out_size >= (long long)N * D + E);
    int NBe2 = do_keep ? ((E + 1) / 2 + 255) / 256 : 0;
    float* keep = out + (size_t)N * D;
    finish_kernel<<<NBn + NBe2, 256>>>(x, ei, out, keep, N, E, NBn);
}

// round 9
// speedup vs baseline: 1.2625x; 1.0197x over previous
#include <cuda_runtime.h>
#include <cuda_bf16.h>

// RobustPrompt_I: graph prompt + edge pruning
//  in: x[N,128] f32, edge_index[2,E] i32, p_sim[1,128], p_deg[1,128], p_other[1,128]
//  out: x_new[N,128] f32  ++  keep[E] (0/1 as f32)

#define D        128
#define D4       32
#define NCAP     131072
#define ECAP     1048576
#define SIM_THR  0.2f
#define DEG_THR  3.0f
#define PT_THR   0.1f
#define EPSV     1e-8f

#define NBE      2048        // persistent edge blocks in big_kernel

// packed per-node record: [0] = (csum, deg, 0, 0)   [1] = (d0, d1, d2, ||x||^2)
__device__ float4 g_rec[NCAP][2];
__device__ float  g_dot[ECAP];     // raw dot(x_r, x_c) per edge
__device__ float  g_W[4][4];       // combo -> weight triple over prompts (row=float4)
__device__ float  g_GC[4][4];      // delta_a · delta_b LUT
__device__ float4 g_delta[4][D4];  // the 4 possible delta rows

// ---------- setup body (1 warp): nz flags, Gram, weights, delta rows, LUTs ----------
__device__ __forceinline__ void setup_body(const float* __restrict__ ps,
                                           const float* __restrict__ pd,
                                           const float* __restrict__ po,
                                           int lane) {
    unsigned full = 0xFFFFFFFFu;
    float4 P[3];
    P[0] = reinterpret_cast<const float4*>(ps)[lane];
    P[1] = reinterpret_cast<const float4*>(pd)[lane];
    P[2] = reinterpret_cast<const float4*>(po)[lane];

    int nz[3];
    #pragma unroll
    for (int k = 0; k < 3; k++) {
        bool z = (P[k].x != 0.f) & (P[k].y != 0.f) & (P[k].z != 0.f) & (P[k].w != 0.f);
        nz[k] = __all_sync(full, z);
    }
    float G[3][3];
    #pragma unroll
    for (int a = 0; a < 3; a++)
        #pragma unroll
        for (int b = 0; b < 3; b++) {
            float s = P[a].x * P[b].x + P[a].y * P[b].y + P[a].z * P[b].z + P[a].w * P[b].w;
            #pragma unroll
            for (int o = 16; o > 0; o >>= 1) s += __shfl_xor_sync(full, s, o);
            G[a][b] = s;
        }
    float W[4][3];
    #pragma unroll
    for (int idx = 0; idx < 4; idx++) {
        int msim = idx & 1, mdeg = (idx >> 1) & 1, moth = (idx == 0);
        int plen = msim * nz[0] + mdeg * nz[1] + moth * nz[2];
        float inv = (plen > 0) ? (1.0f / (float)plen) : 0.0f;
        W[idx][0] = (float)msim * inv;
        W[idx][1] = (float)mdeg * inv;
        W[idx][2] = (float)moth * inv;
        float4 dl;
        dl.x = W[idx][0]*P[0].x + W[idx][1]*P[1].x + W[idx][2]*P[2].x;
        dl.y = W[idx][0]*P[0].y + W[idx][1]*P[1].y + W[idx][2]*P[2].y;
        dl.z = W[idx][0]*P[0].z + W[idx][1]*P[1].z + W[idx][2]*P[2].z;
        dl.w = W[idx][0]*P[0].w + W[idx][1]*P[1].w + W[idx][2]*P[2].w;
        g_delta[idx][lane] = dl;
    }
    if (lane == 0) {
        for (int idx = 0; idx < 4; idx++) {
            g_W[idx][0] = W[idx][0]; g_W[idx][1] = W[idx][1];
            g_W[idx][2] = W[idx][2]; g_W[idx][3] = 0.f;
        }
        for (int a = 0; a < 4; a++)
            for (int b = 0; b < 4; b++) {
                float s = 0.f;
                for (int k = 0; k < 3; k++)
                    for (int j = 0; j < 3; j++)
                        s += W[a][k] * G[k][j] * W[b][j];
                g_GC[a][b] = s;
            }
    }
}

// ---------- K1: edges (pipelined gather+dot+norms+scatter) | setup | node stats ----------
__global__ void big_kernel(const float* __restrict__ x,
                           const int* __restrict__ ei,
                           const float* __restrict__ ps,
                           const float* __restrict__ pd,
                           const float* __restrict__ po,
                           int n, int E) {
    const float4* X = reinterpret_cast<const float4*>(x);
    int bid = blockIdx.x;
    if (bid < NBE) {
        int sub     = threadIdx.x & 7;
        int group   = bid * 32 + (threadIdx.x >> 3);
        int ngroups = NBE * 32;

        int e = group;
        int r = 0, c = 0;
        if (e < E) { r = __ldg(&ei[e]); c = __ldg(&ei[E + e]); }
        while (e < E) {
            const float4* Ar = X + (size_t)r * D4 + sub;
            const float4* Bc = X + (size_t)c * D4 + sub;
            float4 a[4], b[4];
            #pragma unroll
            for (int k = 0; k < 4; k++) a[k] = __ldg(Ar + 8 * k);
            #pragma unroll
            for (int k = 0; k < 4; k++) b[k] = __ldg(Bc + 8 * k);

            int en = e + ngroups;
            int rn = 0, cn = 0;
            if (en < E) { rn = __ldg(&ei[en]); cn = __ldg(&ei[E + en]); }

            float s = 0.f, nr = 0.f, nc = 0.f;
            #pragma unroll
            for (int k = 0; k < 4; k++) {
                s  += a[k].x*b[k].x + a[k].y*b[k].y + a[k].z*b[k].z + a[k].w*b[k].w;
                nr += a[k].x*a[k].x + a[k].y*a[k].y + a[k].z*a[k].z + a[k].w*a[k].w;
                nc += b[k].x*b[k].x + b[k].y*b[k].y + b[k].z*b[k].z + b[k].w*b[k].w;
            }
            #pragma unroll
            for (int o = 4; o > 0; o >>= 1) {
                s  += __shfl_xor_sync(0xFFFFFFFFu, s,  o);
                nr += __shfl_xor_sync(0xFFFFFFFFu, nr, o);
                nc += __shfl_xor_sync(0xFFFFFFFFu, nc, o);
            }
            if (sub == 0) {
                g_dot[e] = s;
                float sn = s * rsqrtf(nr) * rsqrtf(nc);
                float* rec = reinterpret_cast<float*>(&g_rec[c][0]);
                atomicAdd(rec,     sn);
                atomicAdd(rec + 1, 1.0f);
            }
            e = en; r = rn; c = cn;
        }
    } else if (bid == NBE) {
        if (threadIdx.x < 32) setup_body(ps, pd, po, threadIdx.x);
    } else {
        int w    = ((bid - NBE - 1) * blockDim.x + threadIdx.x) >> 5;
        int lane = threadIdx.x & 31;
        if (w >= n) return;
        float4 xv = X[(size_t)w * D4 + lane];
        float4 P0 = reinterpret_cast<const float4*>(ps)[lane];
        float4 P1 = reinterpret_cast<const float4*>(pd)[lane];
        float4 P2 = reinterpret_cast<const float4*>(po)[lane];

        float ss = xv.x*xv.x + xv.y*xv.y + xv.z*xv.z + xv.w*xv.w;
        float d0 = xv.x*P0.x + xv.y*P0.y + xv.z*P0.z + xv.w*P0.w;
        float d1 = xv.x*P1.x + xv.y*P1.y + xv.z*P1.z + xv.w*P1.w;
        float d2 = xv.x*P2.x + xv.y*P2.y + xv.z*P2.z + xv.w*P2.w;
        #pragma unroll
        for (int o = 16; o > 0; o >>= 1) {
            ss += __shfl_xor_sync(0xFFFFFFFFu, ss, o);
            d0 += __shfl_xor_sync(0xFFFFFFFFu, d0, o);
            d1 += __shfl_xor_sync(0xFFFFFFFFu, d1, o);
            d2 += __shfl_xor_sync(0xFFFFFFFFu, d2, o);
        }
        if (lane == 0) g_rec[w][1] = make_float4(d0, d1, d2, ss);
    }
}

// combo index from per-node (csum, deg) — bit-identical to reference masks
__device__ __forceinline__ int combo_of(float csum, float deg) {
    bool msim = (deg > 0.f) && ((csum / deg) <= SIM_THR);
    bool mdeg = (deg <= DEG_THR);
    return (int)msim | ((int)mdeg << 1);
}

// per-edge keep from packed endpoint records
__device__ __forceinline__ float edge_keep(float dot, float4 cdr, float4 Ar,
                                           float4 cdc, float4 Ac) {
    int cr = combo_of(cdr.x, cdr.y);
    int cc = combo_of(cdc.x, cdc.y);
    float4 Wr = *reinterpret_cast<const float4*>(&g_W[cr][0]);
    float4 Wc = *reinterpret_cast<const float4*>(&g_W[cc][0]);
    float xddr = Wr.x*Ar.x + Wr.y*Ar.y + Wr.z*Ar.z;
    float xddc = Wc.x*Ac.x + Wc.y*Ac.y + Wc.z*Ac.z;
    float nr2 = Ar.w + 2.0f * xddr + g_GC[cr][cr];
    float nc2 = Ac.w + 2.0f * xddc + g_GC[cc][cc];
    float rir = 1.0f / fmaxf(sqrtf(fmaxf(nr2, 0.f)), EPSV);
    float ric = 1.0f / fmaxf(sqrtf(fmaxf(nc2, 0.f)), EPSV);
    float num = dot
              + Ar.x * Wc.x + Ar.y * Wc.y + Ar.z * Wc.z
              + Ac.x * Wr.x + Ac.y * Wr.y + Ac.z * Wr.z
              + g_GC[cr][cc];
    float cosv = num * rir * ric;
    return (cosv >= PT_THR) ? 1.0f : 0.0f;
}

// ---------- K2 finish: node write (MLP4) | edge2 (2 edges/thread, packed recs) ----------
__global__ void finish_kernel(const float* __restrict__ x,
                              const int* __restrict__ ei,
                              float* __restrict__ out,
                              float* __restrict__ keep,
                              int n, int E, int NBn) {
    if ((int)blockIdx.x < NBn) {
        int tid  = threadIdx.x;
        int node = blockIdx.x * 32 + (tid >> 3);
        if (node >= n) return;
        int j = tid & 7;
        float4 cd = g_rec[node][0];
        int idx = combo_of(cd.x, cd.y);
        const float4* Xr = reinterpret_cast<const float4*>(x) + (size_t)node * D4;
        float4 xv0 = __ldcs(Xr + j);
        float4 xv1 = __ldcs(Xr + j + 8);
        float4 xv2 = __ldcs(Xr + j + 16);
        float4 xv3 = __ldcs(Xr + j + 24);
        float4 dl0 = g_delta[idx][j];
        float4 dl1 = g_delta[idx][j + 8];
        float4 dl2 = g_delta[idx][j + 16];
        float4 dl3 = g_delta[idx][j + 24];
        xv0.x += dl0.x; xv0.y += dl0.y; xv0.z += dl0.z; xv0.w += dl0.w;
        xv1.x += dl1.x; xv1.y += dl1.y; xv1.z += dl1.z; xv1.w += dl1.w;
        xv2.x += dl2.x; xv2.y += dl2.y; xv2.z += dl2.z; xv2.w += dl2.w;
        xv3.x += dl3.x; xv3.y += dl3.y; xv3.z += dl3.z; xv3.w += dl3.w;
        float4* Or = reinterpret_cast<float4*>(out) + (size_t)node * D4;
        __stcs(Or + j,      xv0);
        __stcs(Or + j + 8,  xv1);
        __stcs(Or + j + 16, xv2);
        __stcs(Or + j + 24, xv3);
    } else {
        // ---- edge2: 2 edges/thread, packed 32B records per endpoint ----
        int t  = (blockIdx.x - NBn) * blockDim.x + threadIdx.x;
        int e0 = t * 2;
        int e1 = e0 + 1;
        if (e0 >= E) return;
        bool has1 = (e1 < E);

        int r0 = __ldg(&ei[e0]);
        int c0 = __ldg(&ei[E + e0]);
        int r1 = has1 ? __ldg(&ei[e1]) : r0;
        int c1 = has1 ? __ldg(&ei[E + e1]) : c0;
        float dt0 = g_dot[e0];
        float dt1 = has1 ? g_dot[e1] : 0.f;

        // each endpoint: two adjacent LDG.128 in the same 32B-pair sector
        float4 cdr0 = g_rec[r0][0], Ar0 = g_rec[r0][1];
        float4 cdc0 = g_rec[c0][0], Ac0 = g_rec[c0][1];
        float4 cdr1 = g_rec[r1][0], Ar1 = g_rec[r1][1];
        float4 cdc1 = g_rec[c1][0], Ac1 = g_rec[c1][1];

        keep[e0] = edge_keep(dt0, cdr0, Ar0, cdc0, Ac0);
        if (has1) keep[e1] = edge_keep(dt1, cdr1, Ar1, cdc1, Ac1);
    }
}

extern "C" void kernel_launch(void* const* d_in, const int* in_sizes, int n_in,
                              void* d_out, int out_size) {
    const float* x  = (const float*)d_in[0];
    const int*   ei = (const int*)d_in[1];
    const float* ps = (const float*)d_in[2];
    const float* pd = (const float*)d_in[3];
    const float* po = (const float*)d_in[4];
    float* out = (float*)d_out;

    int N = in_sizes[0] / D;
    int E = in_sizes[1] / 2;

    static void* rec_ptr = nullptr;
    if (!rec_ptr) cudaGetSymbolAddress(&rec_ptr, g_rec);
    cudaMemsetAsync(rec_ptr, 0, (size_t)N * 2 * sizeof(float4));

    int NBa = (N + 7) / 8;
    big_kernel<<<NBE + 1 + NBa, 256>>>(x, ei, ps, pd, po, N, E);

    int NBn = (N + 31) / 32;
    bool do_keep = ((long long)out_size >= (long long)N * D + E);
    int NBe2 = do_keep ? ((E + 1) / 2 + 255) / 256 : 0;
    float* keep = out + (size_t)N * D;
    finish_kernel<<<NBn + NBe2, 256>>>(x, ei, out, keep, N, E, NBn);
}